// round 2
// baseline (speedup 1.0000x reference)
#include <cuda_runtime.h>

#define NN 64
#define CC 128
#define HH 64
#define WW 64
#define HID 8

// Scratch (device globals). All fully rewritten every call -> deterministic.
__device__ float g_gap[NN][CC];          // per-(n,c) spatial mean
__device__ float g_pool[NN][CC][16];     // per-(n,c) 4x4 pooled means
__device__ float g_sp[NN][9];
__device__ float g_co[NN][CC];
__device__ float g_ci[NN][CC];
__device__ float g_z[NN][HH][WW];        // ci-weighted channel reduction
__device__ float g_t[NN][HH][WW];        // conv3x3(z, sp)

// ---------------------------------------------------------------------------
// Kernel A: per (n,c) plane -> spatial mean + 16 pooled means.
// One block per (n,c), 256 threads; thread t = (row r=t/4, quarter q=t%4)
// sums 16 contiguous floats. Pool p = (r/16)*4 + q.
// ---------------------------------------------------------------------------
__global__ void kA_reduce(const float* __restrict__ x) {
    int nc = blockIdx.x;               // n*CC + c
    int t  = threadIdx.x;              // 0..255
    int r  = t >> 2;                   // row 0..63
    int q  = t & 3;                    // quarter 0..3

    const float4* xp = (const float4*)(x + (size_t)nc * (HH * WW));
    float s = 0.f;
#pragma unroll
    for (int j = 0; j < 4; ++j) {
        float4 v = xp[r * 16 + q * 4 + j];
        s += (v.x + v.y) + (v.z + v.w);
    }

    __shared__ float part[256];
    __shared__ float spool[16];
    part[t] = s;
    __syncthreads();

    int n = nc >> 7;
    int c = nc & 127;
    if (t < 16) {
        int pr = t >> 2, pq = t & 3;
        float ps = 0.f;
#pragma unroll
        for (int rr = 0; rr < 16; ++rr)
            ps += part[(pr * 16 + rr) * 4 + pq];
        spool[t] = ps;
        g_pool[n][c][t] = ps * (1.f / 256.f);
    }
    __syncthreads();
    if (t == 0) {
        float tot = 0.f;
#pragma unroll
        for (int p = 0; p < 16; ++p) tot += spool[p];
        g_gap[n][c] = tot * (1.f / (HH * WW));
    }
}

// ---------------------------------------------------------------------------
// Kernel B: per-sample MLPs. One block per n, 128 threads.
// ---------------------------------------------------------------------------
__global__ void kB_mlp(const float* __restrict__ W_sp, const float* __restrict__ b_sp,
                       const float* __restrict__ W_o1, const float* __restrict__ b_o1,
                       const float* __restrict__ W_o2, const float* __restrict__ b_o2,
                       const float* __restrict__ W_i1, const float* __restrict__ b_i1,
                       const float* __restrict__ W_i2, const float* __restrict__ b_i2) {
    int n = blockIdx.x;
    int t = threadIdx.x;               // 0..127

    __shared__ float sg[CC];
    __shared__ float sxs[16];
    __shared__ float sho[HID];
    __shared__ float shi[HID];

    sg[t] = g_gap[n][t];
    if (t < 16) {
        float s = 0.f;
        for (int c = 0; c < CC; ++c) s += g_pool[n][c][t];
        sxs[t] = s * (1.f / CC);
    }
    __syncthreads();

    if (t < HID) {
        float a = b_o1[t];
        float b = b_i1[t];
        for (int c = 0; c < CC; ++c) {
            a += sg[c] * W_o1[c * HID + t];
            b += sg[c] * W_i1[c * HID + t];
        }
        sho[t] = fmaxf(a, 0.f);
        shi[t] = fmaxf(b, 0.f);
    }
    __syncthreads();

    float a = b_o2[t];
    float b = b_i2[t];
#pragma unroll
    for (int j = 0; j < HID; ++j) {
        a += sho[j] * W_o2[j * CC + t];
        b += shi[j] * W_i2[j * CC + t];
    }
    g_co[n][t] = a;
    g_ci[n][t] = b;

    if (t < 9) {
        float s = b_sp[t];
#pragma unroll
        for (int p = 0; p < 16; ++p) s += sxs[p] * W_sp[p * 9 + t];
        g_sp[n][t] = s;
    }
}

// ---------------------------------------------------------------------------
// Kernel C: z[n,h,w] = sum_i ci[n,i] * x[n,i,h,w]
// float4 version: grid (8, N), 128 threads. Each thread owns one float4
// column across all 128 channels (stride = plane size). Warp issues 512B
// contiguous per iteration; unroll 8 -> deep MLP.
// ---------------------------------------------------------------------------
__global__ void kC_chanreduce(const float4* __restrict__ x) {
    int n     = blockIdx.y;
    int chunk = blockIdx.x;            // 0..7
    int t     = threadIdx.x;           // 0..127

    __shared__ float sci[CC];
    sci[t] = g_ci[n][t];
    __syncthreads();

    int q = chunk * 128 + t;           // float4 index in plane (0..1023)
    const float4* xp = x + (size_t)n * CC * (HH * WW / 4) + q;
    float4 acc = make_float4(0.f, 0.f, 0.f, 0.f);
#pragma unroll 8
    for (int i = 0; i < CC; ++i) {
        float4 v = xp[(size_t)i * (HH * WW / 4)];
        float s = sci[i];
        acc.x += s * v.x; acc.y += s * v.y;
        acc.z += s * v.z; acc.w += s * v.w;
    }
    ((float4*)g_z)[n * (HH * WW / 4) + q] = acc;
}

// ---------------------------------------------------------------------------
// Kernel D: t = conv3x3(z, sp), zero padding. grid (4 row-chunks, N),
// 256 threads. 18 rows (16 + halo) staged in smem, 4 outputs/thread.
// ---------------------------------------------------------------------------
__global__ void kD_conv(void) {
    int n     = blockIdx.y;
    int chunk = blockIdx.x;            // 0..3 -> output rows [chunk*16, +16)
    int t     = threadIdx.x;           // 0..255

    __shared__ float sz[18][WW];
    __shared__ float ssp[9];

    int r0 = chunk * 16 - 1;
    // load 18 rows x 16 float4 = 288 quads
    for (int k = t; k < 18 * 16; k += 256) {
        int rr = k >> 4, qq = k & 15;
        int h = r0 + rr;
        float4 v = make_float4(0.f, 0.f, 0.f, 0.f);
        if (h >= 0 && h < HH)
            v = ((const float4*)g_z)[(n * HH + h) * 16 + qq];
        ((float4*)&sz[rr][0])[qq] = v;
    }
    if (t < 9) ssp[t] = g_sp[n][t];
    __syncthreads();

#pragma unroll
    for (int k = 0; k < 4; ++k) {
        int p = t + k * 256;           // 0..1023
        int h = p >> 6, w = p & 63;    // local row 0..15
        float acc = 0.f;
#pragma unroll
        for (int kh = 0; kh < 3; ++kh) {
#pragma unroll
            for (int kw = 0; kw < 3; ++kw) {
                int ww = w + kw - 1;
                if (ww >= 0 && ww < WW)
                    acc += ssp[kh * 3 + kw] * sz[h + kh][ww];
            }
        }
        g_t[n][chunk * 16 + h][w] = acc;
    }
}

// ---------------------------------------------------------------------------
// Kernel E: y[n,o,h,w] = co[n,o] * t[n,h,w]  (134 MB float4 store; t in L2)
// ---------------------------------------------------------------------------
__global__ void kE_scale(float4* __restrict__ out) {
    long idx = (long)blockIdx.x * blockDim.x + threadIdx.x;  // float4 index
    int w4 = (int)(idx & 15);
    long r = idx >> 4;
    int h = (int)(r & 63);
    r >>= 6;
    int o = (int)(r & 127);
    int n = (int)(r >> 7);

    const float4* tp = (const float4*)g_t;
    float4 v = tp[(n * 64 + h) * 16 + w4];
    float s = g_co[n][o];
    float4 ov;
    ov.x = v.x * s; ov.y = v.y * s; ov.z = v.z * s; ov.w = v.w * s;
    out[idx] = ov;
}

// ---------------------------------------------------------------------------
extern "C" void kernel_launch(void* const* d_in, const int* in_sizes, int n_in,
                              void* d_out, int out_size) {
    const float* x    = (const float*)d_in[0];
    const float* W_sp = (const float*)d_in[1];
    const float* b_sp = (const float*)d_in[2];
    const float* W_o1 = (const float*)d_in[3];
    const float* b_o1 = (const float*)d_in[4];
    const float* W_o2 = (const float*)d_in[5];
    const float* b_o2 = (const float*)d_in[6];
    const float* W_i1 = (const float*)d_in[7];
    const float* b_i1 = (const float*)d_in[8];
    const float* W_i2 = (const float*)d_in[9];
    const float* b_i2 = (const float*)d_in[10];

    kA_reduce<<<NN * CC, 256>>>(x);
    kB_mlp<<<NN, CC>>>(W_sp, b_sp, W_o1, b_o1, W_o2, b_o2,
                       W_i1, b_i1, W_i2, b_i2);
    {
        dim3 g(8, NN);
        kC_chanreduce<<<g, 128>>>((const float4*)x);
    }
    {
        dim3 g(4, NN);
        kD_conv<<<g, 256>>>();
    }
    {
        long total4 = (long)NN * CC * HH * WW / 4;   // 8,388,608
        kE_scale<<<(unsigned)(total4 / 256), 256>>>((float4*)d_out);
    }
}

// round 3
// speedup vs baseline: 1.1662x; 1.1662x over previous
#include <cuda_runtime.h>

#define NN 64
#define CC 128
#define HH 64
#define WW 64
#define HID 8

// Scratch (device globals). All fully rewritten every call -> deterministic.
__device__ float g_gap[NN][CC];          // per-(n,c) spatial mean
__device__ float g_pool[NN][CC][16];     // per-(n,c) 4x4 pooled means
__device__ float g_sp[NN][9];
__device__ float g_co[NN][CC];
__device__ float g_ci[NN][CC];
__device__ float g_z[NN][HH][WW];        // ci-weighted channel reduction

// ---------------------------------------------------------------------------
// Kernel A: per (n,c) plane -> spatial mean + 16 pooled means.
// One block per (n,c), 256 threads; thread t = (row r=t/4, quarter q=t%4)
// sums 16 contiguous floats. Pool p = (r/16)*4 + q.
// ---------------------------------------------------------------------------
__global__ void kA_reduce(const float* __restrict__ x) {
    int nc = blockIdx.x;               // n*CC + c
    int t  = threadIdx.x;              // 0..255
    int r  = t >> 2;                   // row 0..63
    int q  = t & 3;                    // quarter 0..3

    const float4* xp = (const float4*)(x + (size_t)nc * (HH * WW));
    float s = 0.f;
#pragma unroll
    for (int j = 0; j < 4; ++j) {
        float4 v = xp[r * 16 + q * 4 + j];
        s += (v.x + v.y) + (v.z + v.w);
    }

    __shared__ float part[256];
    __shared__ float spool[16];
    part[t] = s;
    __syncthreads();

    int n = nc >> 7;
    int c = nc & 127;
    if (t < 16) {
        int pr = t >> 2, pq = t & 3;
        float ps = 0.f;
#pragma unroll
        for (int rr = 0; rr < 16; ++rr)
            ps += part[(pr * 16 + rr) * 4 + pq];
        spool[t] = ps;
        g_pool[n][c][t] = ps * (1.f / 256.f);
    }
    __syncthreads();
    if (t == 0) {
        float tot = 0.f;
#pragma unroll
        for (int p = 0; p < 16; ++p) tot += spool[p];
        g_gap[n][c] = tot * (1.f / (HH * WW));
    }
}

// ---------------------------------------------------------------------------
// Kernel B: per-sample MLPs. One block per n, 128 threads.
// ---------------------------------------------------------------------------
__global__ void kB_mlp(const float* __restrict__ W_sp, const float* __restrict__ b_sp,
                       const float* __restrict__ W_o1, const float* __restrict__ b_o1,
                       const float* __restrict__ W_o2, const float* __restrict__ b_o2,
                       const float* __restrict__ W_i1, const float* __restrict__ b_i1,
                       const float* __restrict__ W_i2, const float* __restrict__ b_i2) {
    int n = blockIdx.x;
    int t = threadIdx.x;               // 0..127

    __shared__ float sg[CC];
    __shared__ float sxs[16];
    __shared__ float sho[HID];
    __shared__ float shi[HID];

    sg[t] = g_gap[n][t];
    if (t < 16) {
        float s = 0.f;
        for (int c = 0; c < CC; ++c) s += g_pool[n][c][t];
        sxs[t] = s * (1.f / CC);
    }
    __syncthreads();

    if (t < HID) {
        float a = b_o1[t];
        float b = b_i1[t];
        for (int c = 0; c < CC; ++c) {
            a += sg[c] * W_o1[c * HID + t];
            b += sg[c] * W_i1[c * HID + t];
        }
        sho[t] = fmaxf(a, 0.f);
        shi[t] = fmaxf(b, 0.f);
    }
    __syncthreads();

    float a = b_o2[t];
    float b = b_i2[t];
#pragma unroll
    for (int j = 0; j < HID; ++j) {
        a += sho[j] * W_o2[j * CC + t];
        b += shi[j] * W_i2[j * CC + t];
    }
    g_co[n][t] = a;
    g_ci[n][t] = b;

    if (t < 9) {
        float s = b_sp[t];
#pragma unroll
        for (int p = 0; p < 16; ++p) s += sxs[p] * W_sp[p * 9 + t];
        g_sp[n][t] = s;
    }
}

// ---------------------------------------------------------------------------
// Kernel C: z[n,h,w] = sum_i ci[n,i] * x[n,i,h,w]
// Round-1 shape (known good): grid (H, N) = 4096 blocks, 64 threads = one
// output row. 8192 warps chip-wide for latency hiding; unroll 8 for MLP.
// ---------------------------------------------------------------------------
__global__ void kC_chanreduce(const float* __restrict__ x) {
    int h = blockIdx.x;
    int n = blockIdx.y;
    int w = threadIdx.x;               // 0..63

    __shared__ float sci[CC];
    sci[w]      = g_ci[n][w];
    sci[w + 64] = g_ci[n][w + 64];
    __syncthreads();

    const float* xp = x + ((size_t)n * CC) * (HH * WW) + h * WW + w;
    float acc = 0.f;
#pragma unroll 8
    for (int i = 0; i < CC; ++i)
        acc += sci[i] * xp[(size_t)i * (HH * WW)];
    g_z[n][h][w] = acc;
}

// ---------------------------------------------------------------------------
// Fused kernel DE: per block (row-chunk, n):
//   1) stage z rows [r0-1, r0+8] in smem (zero-padded)
//   2) compute t tile = conv3x3(z, sp) for 8 rows (once)
//   3) sweep all 128 output channels: out[n,o,rows,:] = co[n,o] * t
// grid (8, NN) = 512 blocks, 256 threads. Store-bound (134 MB total).
// ---------------------------------------------------------------------------
__global__ void kDE_convscale(float4* __restrict__ out) {
    int chunk = blockIdx.x;            // 0..7 -> output rows [chunk*8, +8)
    int n     = blockIdx.y;
    int t     = threadIdx.x;           // 0..255

    __shared__ float sz[10][WW];       // rows r0-1 .. r0+8
    __shared__ float st[8][WW];        // conv result tile
    __shared__ float sco[CC];
    __shared__ float ssp[9];

    int r0 = chunk * 8;

    // stage z rows with halo: 10 rows x 16 quads = 160 quads
    if (t < 160) {
        int rr = t >> 4, qq = t & 15;
        int h = r0 - 1 + rr;
        float4 v = make_float4(0.f, 0.f, 0.f, 0.f);
        if (h >= 0 && h < HH)
            v = ((const float4*)g_z)[(n * HH + h) * 16 + qq];
        ((float4*)&sz[rr][0])[qq] = v;
    }
    if (t < CC) sco[t] = g_co[n][t];
    if (t >= 240 && t < 249) ssp[t - 240] = g_sp[n][t - 240];
    __syncthreads();

    // conv: 8*64 = 512 outputs, 2 per thread
#pragma unroll
    for (int k = 0; k < 2; ++k) {
        int p = t + k * 256;           // 0..511
        int h = p >> 6, w = p & 63;    // local row 0..7
        float acc = 0.f;
#pragma unroll
        for (int kh = 0; kh < 3; ++kh) {
#pragma unroll
            for (int kw = 0; kw < 3; ++kw) {
                int ww = w + kw - 1;
                if (ww >= 0 && ww < WW)
                    acc += ssp[kh * 3 + kw] * sz[h + kh][ww];
            }
        }
        st[h][w] = acc;
    }
    __syncthreads();

    // broadcast-scale write: each thread owns one quad of the tile and one
    // o-half; loops 64 output channels. Stores contiguous per 128-thread half.
    int q  = t & 127;                  // quad within tile: rr=q>>4, qq=q&15
    int og = t >> 7;                   // 0 or 1
    float4 v = ((const float4*)st)[q];
    int rr = q >> 4, qq = q & 15;

    size_t base = ((size_t)n * CC + og * 64) * (HH * WW / 4)
                + (size_t)(r0 + rr) * 16 + qq;
#pragma unroll 4
    for (int o = 0; o < 64; ++o) {
        float s = sco[og * 64 + o];
        float4 ov;
        ov.x = v.x * s; ov.y = v.y * s; ov.z = v.z * s; ov.w = v.w * s;
        out[base + (size_t)o * (HH * WW / 4)] = ov;
    }
}

// ---------------------------------------------------------------------------
extern "C" void kernel_launch(void* const* d_in, const int* in_sizes, int n_in,
                              void* d_out, int out_size) {
    const float* x    = (const float*)d_in[0];
    const float* W_sp = (const float*)d_in[1];
    const float* b_sp = (const float*)d_in[2];
    const float* W_o1 = (const float*)d_in[3];
    const float* b_o1 = (const float*)d_in[4];
    const float* W_o2 = (const float*)d_in[5];
    const float* b_o2 = (const float*)d_in[6];
    const float* W_i1 = (const float*)d_in[7];
    const float* b_i1 = (const float*)d_in[8];
    const float* W_i2 = (const float*)d_in[9];
    const float* b_i2 = (const float*)d_in[10];

    kA_reduce<<<NN * CC, 256>>>(x);
    kB_mlp<<<NN, CC>>>(W_sp, b_sp, W_o1, b_o1, W_o2, b_o2,
                       W_i1, b_i1, W_i2, b_i2);
    {
        dim3 g(HH, NN);
        kC_chanreduce<<<g, WW>>>(x);
    }
    {
        dim3 g(8, NN);
        kDE_convscale<<<g, 256>>>((float4*)d_out);
    }
}